// round 14
// baseline (speedup 1.0000x reference)
#include <cuda_runtime.h>
#include <cstdint>
#include <cfloat>

#define NPTS 8192
#define BB 2
#define RR 2048
#define KK 16
#define CINC 64
#define CLC 16
#define COUTC 128
#define KSQ 256
#define NGRP (BB*RR)      /* 4096 */
#define FEATC 80          /* CLC + CINC */
#define FLEN 1280         /* KK*FEATC */

// ---------------- scratch (device globals; no allocation allowed) ----------------
__device__ float g_feat[NGRP*FLEN];
__device__ float g_T[NGRP*KSQ];
__device__ int   g_nb[NGRP*KK];
__device__ float g_sq[BB*NPTS];
// tf32 split (hi, lo) operands
__device__ uint2 g_pfs[NGRP*48];
__device__ uint2 g_h1s[NGRP*KSQ];
__device__ uint2 g_h2s[NGRP*KSQ];
__device__ uint2 g_Tfs[NGRP*FLEN];
__device__ uint2 g_t1ws[KSQ*48];
__device__ uint2 g_t2ws[KSQ*KSQ];
__device__ uint2 g_t3ws[KSQ*KSQ];
__device__ uint2 g_cws[COUTC*FLEN];

// ---------------- tf32x3 helpers ----------------
__device__ __forceinline__ void f2tf32x2(float x, uint32_t& hi, uint32_t& lo) {
    asm("cvt.rna.tf32.f32 %0, %1;" : "=r"(hi) : "f"(x));
    const float l = __fsub_rn(x, __uint_as_float(hi));
    asm("cvt.rna.tf32.f32 %0, %1;" : "=r"(lo) : "f"(l));
}
__device__ __forceinline__ uint2 f2split(float x) {
    uint32_t h, l; f2tf32x2(x, h, l); return make_uint2(h, l);
}
__device__ __forceinline__ void mma_tf32(float* c, const uint32_t* a, const uint32_t* b) {
    asm volatile("mma.sync.aligned.m16n8k8.row.col.f32.tf32.tf32.f32 "
        "{%0,%1,%2,%3}, {%4,%5,%6,%7}, {%8,%9}, {%0,%1,%2,%3};"
        : "+f"(c[0]), "+f"(c[1]), "+f"(c[2]), "+f"(c[3])
        : "r"(a[0]), "r"(a[1]), "r"(a[2]), "r"(a[3]), "r"(b[0]), "r"(b[1]));
}

// ---------------- sq = sum(points*points, -1), canonical XLA rounding (no FMA) ----------------
__global__ void sq_kernel(const float* __restrict__ points) {
    const int i = blockIdx.x*256 + threadIdx.x;
    if (i < BB*NPTS) {
        const float x = points[i*3+0], y = points[i*3+1], z = points[i*3+2];
        g_sq[i] = __fadd_rn(__fadd_rn(__fmul_rn(x,x), __fmul_rn(y,y)), __fmul_rn(z,z));
    }
}

// ---------------- KNN: top-17 (ascending d2, stable index tie-break), drop self ----------------
__global__ void knn_kernel(const float* __restrict__ points, const int* __restrict__ rep_idx) {
    const int b = blockIdx.y;
    const float* __restrict__ P  = points + (size_t)b * NPTS * 3;
    const float* __restrict__ SQ = g_sq + (size_t)b * NPTS;
    __shared__ float swv[8];
    __shared__ int   swi[8];
    __shared__ int   s_gi;
    __shared__ int   s_nb[17];
    const int tid  = threadIdx.x;          // 256 threads
    const int lane = tid & 31;
    const int warp = tid >> 5;

    for (int r = blockIdx.x; r < RR; r += gridDim.x) {
        const int rp = rep_idx[r];
        const float qx = P[rp*3+0], qy = P[rp*3+1], qz = P[rp*3+2];
        const float sqq = SQ[rp];

        float dloc[32];                    // thread-private candidate distances
        float bv = FLT_MAX; int bi = 0x7FFFFFFF;
        #pragma unroll 4
        for (int i = 0; i < 32; i++) {
            const int j = tid + (i << 8);
            const float px = P[j*3+0], py = P[j*3+1], pz = P[j*3+2];
            float dt = __fmul_rn(px, qx);
            dt = __fmaf_rn(py, qy, dt);
            dt = __fmaf_rn(pz, qz, dt);
            const float d2 = __fsub_rn(__fadd_rn(sqq, SQ[j]), __fmul_rn(2.0f, dt));
            dloc[i] = d2;
            if (d2 < bv) { bv = d2; bi = j; }
        }

        for (int round = 0; round < 17; round++) {
            float v = bv; int ii = bi;
            #pragma unroll
            for (int off = 16; off > 0; off >>= 1) {
                const float ov = __shfl_down_sync(0xFFFFFFFFu, v, off);
                const int   oi = __shfl_down_sync(0xFFFFFFFFu, ii, off);
                if (ov < v || (ov == v && oi < ii)) { v = ov; ii = oi; }
            }
            if (lane == 0) { swv[warp] = v; swi[warp] = ii; }
            __syncthreads();
            if (warp == 0) {
                v  = (lane < 8) ? swv[lane] : FLT_MAX;
                ii = (lane < 8) ? swi[lane] : 0x7FFFFFFF;
                #pragma unroll
                for (int off = 4; off > 0; off >>= 1) {
                    const float ov = __shfl_down_sync(0xFFFFFFFFu, v, off);
                    const int   oi = __shfl_down_sync(0xFFFFFFFFu, ii, off);
                    if (ov < v || (ov == v && oi < ii)) { v = ov; ii = oi; }
                }
                if (lane == 0) { s_gi = ii; s_nb[round] = ii; }
            }
            __syncthreads();
            const int wi = s_gi;
            if (bi == wi) {                      // only the winner rescans its 32
                dloc[(wi - tid) >> 8] = FLT_MAX;
                bv = FLT_MAX; bi = 0x7FFFFFFF;
                #pragma unroll
                for (int i = 0; i < 32; i++) {
                    if (dloc[i] < bv) { bv = dloc[i]; bi = tid + (i << 8); }
                }
            }
        }
        __syncthreads();
        if (tid < KK) g_nb[((size_t)(b*RR + r))*KK + tid] = s_nb[tid + 1];  // drop self
        __syncthreads();
    }
}

// ---------------- gather + p/pf(split) + lifted + feat concat + rep_pos ----------------
__global__ void assemble_kernel(const float* __restrict__ points, const float* __restrict__ features,
                                const float* __restrict__ lift_w, const float* __restrict__ lift_b,
                                const float* __restrict__ bn_g,   const float* __restrict__ bn_b,
                                const int* __restrict__ rep_idx,  float* __restrict__ rep_pos_out) {
    const int g = blockIdx.x;                     // 0..4095
    const int b = g / RR, r = g % RR;
    const int tid = threadIdx.x;                  // 128
    __shared__ float p[KK][3];
    __shared__ int   nj[KK];
    __shared__ float q[3];

    if (tid < KK) nj[tid] = g_nb[(size_t)g*KK + tid];
    if (tid >= 32 && tid < 35) {
        const int rp = rep_idx[r];
        q[tid-32] = points[((size_t)b*NPTS + rp)*3 + (tid-32)];
    }
    __syncthreads();

    if (tid < 48) {
        const int k = tid / 3, d = tid % 3;
        const float val = points[((size_t)b*NPTS + nj[k])*3 + d] - q[d];
        p[k][d] = val;
        g_pfs[(size_t)g*48 + tid] = f2split(val);
    }
    if (tid >= 64 && tid < 67) rep_pos_out[(size_t)g*3 + (tid-64)] = q[tid-64];
    __syncthreads();

    for (int idx = tid; idx < KK*CLC; idx += 128) {
        const int k = idx >> 4, l = idx & 15;
        float v = p[k][0]*lift_w[l*3+0] + p[k][1]*lift_w[l*3+1] + p[k][2]*lift_w[l*3+2];
        v = (v + lift_b[l]) * bn_g[l] + bn_b[l];
        g_feat[(size_t)g*FLEN + k*FEATC + l] = fmaxf(v, 0.0f);
    }
    for (int idx = tid; idx < KK*CINC; idx += 128) {
        const int k = idx >> 6, c = idx & 63;
        g_feat[(size_t)g*FLEN + k*FEATC + CLC + c] = features[((size_t)b*NPTS + nj[k])*CINC + c];
    }
}

// ---------------- tensor-core GEMM (tf32x3, pre-split operands) ----------------
// C[M,N] = A[M,Kd]*W[N,Kd]^T with fused bias/bn/relu epilogue.
// CTA 64x64, 128 threads = 4 warps (2x2), warp tile 32x32. Inner loop: LDS + mma only.
// Smem stride 36 => fragment LDS addr pattern conflict-free.
template<int BK, bool RELU, bool DOBN, bool SPLIT_OUT>
__global__ void gemm_mma_kernel(const uint2* __restrict__ A, const uint2* __restrict__ W,
                                const float* __restrict__ bias, const float* __restrict__ bng,
                                const float* __restrict__ bnb, float* __restrict__ C,
                                uint2* __restrict__ Cs, int M, int N, int Kd) {
    __shared__ uint32_t Ah[64*36], Al[64*36], Bh[64*36], Bl[64*36];
    const int bm = blockIdx.x * 64;
    const int bn = blockIdx.y * 64;
    const int tid = threadIdx.x;                  // 128
    const int lane = tid & 31;
    const int wid  = tid >> 5;
    const int wm = wid & 1, wn = wid >> 1;        // 2x2 warps
    const int gq = lane >> 2;                     // groupID 0..7
    const int tg = lane & 3;                      // thread-in-group 0..3

    float acc[2][4][4];
    #pragma unroll
    for (int a = 0; a < 2; a++)
        #pragma unroll
        for (int b = 0; b < 4; b++)
            #pragma unroll
            for (int c = 0; c < 4; c++) acc[a][b][c] = 0.0f;

    const int NQ = (64*BK/2) / 128;               // uint4 loads (2 elems) per thread per array
    for (int k0 = 0; k0 < Kd; k0 += BK) {
        #pragma unroll
        for (int i = 0; i < NQ; i++) {
            const int idx = tid + 128*i;          // 0 .. 64*BK/2-1
            const int row = idx / (BK/2);
            const int c2  = idx % (BK/2);
            const uint4 av = *(const uint4*)(A + (size_t)(bm + row)*Kd + k0 + c2*2);
            Ah[row*36 + c2*2    ] = av.x; Al[row*36 + c2*2    ] = av.y;
            Ah[row*36 + c2*2 + 1] = av.z; Al[row*36 + c2*2 + 1] = av.w;
            const uint4 bv = *(const uint4*)(W + (size_t)(bn + row)*Kd + k0 + c2*2);
            Bh[row*36 + c2*2    ] = bv.x; Bl[row*36 + c2*2    ] = bv.y;
            Bh[row*36 + c2*2 + 1] = bv.z; Bl[row*36 + c2*2 + 1] = bv.w;
        }
        __syncthreads();

        #pragma unroll
        for (int ks = 0; ks < BK; ks += 8) {
            uint32_t ahi[2][4], alo[2][4], bhi[4][2], blo[4][2];
            #pragma unroll
            for (int mt = 0; mt < 2; mt++) {
                const int m0 = wm*32 + mt*16 + gq;
                ahi[mt][0] = Ah[(m0  )*36 + ks + tg    ];  alo[mt][0] = Al[(m0  )*36 + ks + tg    ];
                ahi[mt][1] = Ah[(m0+8)*36 + ks + tg    ];  alo[mt][1] = Al[(m0+8)*36 + ks + tg    ];
                ahi[mt][2] = Ah[(m0  )*36 + ks + tg + 4];  alo[mt][2] = Al[(m0  )*36 + ks + tg + 4];
                ahi[mt][3] = Ah[(m0+8)*36 + ks + tg + 4];  alo[mt][3] = Al[(m0+8)*36 + ks + tg + 4];
            }
            #pragma unroll
            for (int nt = 0; nt < 4; nt++) {
                const int n0 = wn*32 + nt*8 + gq;
                bhi[nt][0] = Bh[n0*36 + ks + tg    ];  blo[nt][0] = Bl[n0*36 + ks + tg    ];
                bhi[nt][1] = Bh[n0*36 + ks + tg + 4];  blo[nt][1] = Bl[n0*36 + ks + tg + 4];
            }
            #pragma unroll
            for (int mt = 0; mt < 2; mt++)
                #pragma unroll
                for (int nt = 0; nt < 4; nt++) {
                    mma_tf32(acc[mt][nt], alo[mt], bhi[nt]);
                    mma_tf32(acc[mt][nt], ahi[mt], blo[nt]);
                    mma_tf32(acc[mt][nt], ahi[mt], bhi[nt]);
                }
        }
        __syncthreads();
    }

    // epilogue
    #pragma unroll
    for (int mt = 0; mt < 2; mt++) {
        const int row0 = bm + wm*32 + mt*16 + gq;
        #pragma unroll
        for (int nt = 0; nt < 4; nt++) {
            const int col0 = bn + wn*32 + nt*8 + 2*tg;
            float vv[4];
            #pragma unroll
            for (int j = 0; j < 2; j++) {
                const int n = col0 + j;
                const float bia = bias[n];
                float v0 = acc[mt][nt][j]   + bia;
                float v1 = acc[mt][nt][j+2] + bia;
                if (DOBN) {
                    const float gg = bng[n], be = bnb[n];
                    v0 = v0*gg + be; v1 = v1*gg + be;
                }
                if (RELU) { v0 = fmaxf(v0, 0.0f); v1 = fmaxf(v1, 0.0f); }
                vv[j] = v0; vv[j+2] = v1;
            }
            if (SPLIT_OUT) {
                const uint2 s0 = f2split(vv[0]), s1 = f2split(vv[1]);
                const uint2 s2 = f2split(vv[2]), s3 = f2split(vv[3]);
                *(uint4*)&Cs[(size_t)row0*N + col0]     = make_uint4(s0.x, s0.y, s1.x, s1.y);
                *(uint4*)&Cs[(size_t)(row0+8)*N + col0] = make_uint4(s2.x, s2.y, s3.x, s3.y);
            } else {
                *(float2*)&C[(size_t)row0*N + col0]     = make_float2(vv[0], vv[1]);
                *(float2*)&C[(size_t)(row0+8)*N + col0] = make_float2(vv[2], vv[3]);
            }
        }
    }
}

// ---------------- per-group Tf = T[16,16] @ feat[16,80], emits tf32-split ----------------
__global__ void tf_kernel() {
    const int g = blockIdx.x;
    const int tid = threadIdx.x;                  // 128
    __shared__ float Ts[KSQ];
    __shared__ float fs[FLEN];
    for (int i = tid; i < KSQ;  i += 128) Ts[i] = g_T[(size_t)g*KSQ + i];
    for (int i = tid; i < FLEN; i += 128) fs[i] = g_feat[(size_t)g*FLEN + i];
    __syncthreads();
    for (int idx = tid; idx < FLEN; idx += 128) {
        const int k = idx / FEATC, c = idx % FEATC;
        float s = 0.0f;
        #pragma unroll
        for (int j = 0; j < KK; j++) s = fmaf(Ts[k*KK + j], fs[j*FEATC + c], s);
        g_Tfs[(size_t)g*FLEN + idx] = f2split(s);
    }
}

// ---------------- weight split prep ----------------
__global__ void split_kernel(const float* __restrict__ src, uint2* __restrict__ dst, int n) {
    const int i = blockIdx.x*256 + threadIdx.x;
    if (i < n) dst[i] = f2split(src[i]);
}

// ---------------- conv_w [O,C,K] -> g_cws [O, k*80+c] (reorder + split) ----------------
__global__ void prep_cw_kernel(const float* __restrict__ conv_w) {
    const int i = blockIdx.x*256 + threadIdx.x;
    if (i < COUTC*FLEN) {
        const int o = i / FLEN, kc = i % FLEN;
        const int k = kc / FEATC, c = kc % FEATC;
        g_cws[i] = f2split(conv_w[(o*FEATC + c)*KK + k]);
    }
}

// ---------------- launch ----------------
extern "C" void kernel_launch(void* const* d_in, const int* in_sizes, int n_in,
                              void* d_out, int out_size) {
    const float* points   = (const float*)d_in[0];
    const float* features = (const float*)d_in[1];
    const float* lift_w   = (const float*)d_in[2];
    const float* lift_b   = (const float*)d_in[3];
    const float* blg      = (const float*)d_in[4];
    const float* blb      = (const float*)d_in[5];
    const float* t1_w     = (const float*)d_in[6];
    const float* t1_b     = (const float*)d_in[7];
    const float* b1g      = (const float*)d_in[8];
    const float* b1b      = (const float*)d_in[9];
    const float* t2_w     = (const float*)d_in[10];
    const float* t2_b     = (const float*)d_in[11];
    const float* b2g      = (const float*)d_in[12];
    const float* b2b      = (const float*)d_in[13];
    const float* t3_w     = (const float*)d_in[14];
    const float* t3_b     = (const float*)d_in[15];
    const float* b3g      = (const float*)d_in[16];
    const float* b3b      = (const float*)d_in[17];
    const float* conv_w   = (const float*)d_in[18];
    const float* conv_b   = (const float*)d_in[19];
    const int*   rep_idx  = (const int*)d_in[20];
    float* out = (float*)d_out;

    uint2 *pfs, *h1s, *h2s, *Tfs, *t1ws, *t2ws, *t3ws, *cws;
    float *T;
    cudaGetSymbolAddress((void**)&pfs,  g_pfs);
    cudaGetSymbolAddress((void**)&h1s,  g_h1s);
    cudaGetSymbolAddress((void**)&h2s,  g_h2s);
    cudaGetSymbolAddress((void**)&Tfs,  g_Tfs);
    cudaGetSymbolAddress((void**)&t1ws, g_t1ws);
    cudaGetSymbolAddress((void**)&t2ws, g_t2ws);
    cudaGetSymbolAddress((void**)&t3ws, g_t3ws);
    cudaGetSymbolAddress((void**)&cws,  g_cws);
    cudaGetSymbolAddress((void**)&T,    g_T);

    prep_cw_kernel<<<(COUTC*FLEN + 255)/256, 256>>>(conv_w);
    split_kernel<<<(KSQ*48  + 255)/256, 256>>>(t1_w, t1ws, KSQ*48);
    split_kernel<<<(KSQ*KSQ + 255)/256, 256>>>(t2_w, t2ws, KSQ*KSQ);
    split_kernel<<<(KSQ*KSQ + 255)/256, 256>>>(t3_w, t3ws, KSQ*KSQ);
    sq_kernel<<<(BB*NPTS + 255)/256, 256>>>(points);
    knn_kernel<<<dim3(256, BB), 256>>>(points, rep_idx);
    assemble_kernel<<<NGRP, 128>>>(points, features, lift_w, lift_b, blg, blb, rep_idx, out);
    gemm_mma_kernel<16, true,  true,  true ><<<dim3(NGRP/64, KSQ/64),   128>>>(pfs, t1ws, t1_b, b1g, b1b, nullptr, h1s, NGRP, KSQ, 48);
    gemm_mma_kernel<32, true,  true,  true ><<<dim3(NGRP/64, KSQ/64),   128>>>(h1s, t2ws, t2_b, b2g, b2b, nullptr, h2s, NGRP, KSQ, KSQ);
    gemm_mma_kernel<32, false, true,  false><<<dim3(NGRP/64, KSQ/64),   128>>>(h2s, t3ws, t3_b, b3g, b3b, T, nullptr, NGRP, KSQ, KSQ);
    tf_kernel<<<NGRP, 128>>>();
    gemm_mma_kernel<32, false, false, false><<<dim3(NGRP/64, COUTC/64), 128>>>(Tfs, cws, conv_b, nullptr, nullptr,
                                                                               out + (size_t)NGRP*3, nullptr, NGRP, COUTC, FLEN);
}